// round 8
// baseline (speedup 1.0000x reference)
#include <cuda_runtime.h>
#include <cstdint>
#include <math.h>

#define BB 8
#define LC 512
#define LQ 64
#define DD 256
#define TI 32
#define W  32                 // D-chunk width
#define CH (DD / W)           // 8 chunks
#define ST 4                  // cp.async pipeline stages (ctx)
#define SCS 36                // sC row stride (words)
#define SQS 68                // sQT row stride (words)
#define NT 256
#define NEG_BIG 1e30f

__device__ float g_ctx1[BB * LC];
__device__ float g_U[BB * LC];
__device__ float g_m[BB * LC];
__device__ unsigned int g_cnt[BB];

__device__ __forceinline__ void cp16(uint32_t s, const void* g) {
    asm volatile("cp.async.cg.shared.global [%0], [%1], 16;" :: "r"(s), "l"(g));
}
__device__ __forceinline__ void cp_commit() {
    asm volatile("cp.async.commit_group;");
}
__device__ __forceinline__ void cp_wait2() {
    asm volatile("cp.async.wait_group 2;");
}

__global__ __launch_bounds__(NT) void bi_attn_fused(
    const float* __restrict__ ctx, const float* __restrict__ qst,
    const int* __restrict__ mask, const float* __restrict__ att_w,
    const float* __restrict__ att_b, const float* __restrict__ w_in,
    const float* __restrict__ w_mem, float* __restrict__ out)
{
    __shared__ __align__(16) float sC[ST][TI][SCS];    // RAW ctx chunks (cp.async ring)
    __shared__ __align__(16) float sQT[2][W][SQS];     // (w_p * question), transposed [d][j]
    __shared__ __align__(16) float sw[5 * DD];         // wc | w_in | wp | wq | w_mem
    __shared__ float s_sc[TI], s_c1[TI], s_sq[LQ], s_q1[LQ], s_pen[LQ];
    __shared__ float s_red[24];
    __shared__ unsigned s_last;

    const int b   = blockIdx.y;
    const int i0  = blockIdx.x * TI;
    const int tid = threadIdx.x;

    // ---- weights -> smem ----
    for (int i = tid; i < 5 * DD; i += NT) {
        float v;
        if      (i < DD)      v = att_w[i];             // wc
        else if (i < 2 * DD)  v = w_in[i - DD];         // w_in
        else if (i < 3 * DD)  v = att_w[i];             // wp = att_w[512..768)
        else if (i < 4 * DD)  v = att_w[i - 2 * DD];    // wq = att_w[256..512)
        else                  v = w_mem[i - 4 * DD];    // w_mem
        sw[i] = v;
    }
    if (tid < LQ) {
        float mf = (float)mask[b * LQ + tid];
        s_pen[tid] = -NEG_BIG * (1.0f - mf);
    }

    // mappings
    const int cr  = tid >> 3;   // ctx row 0..31 (8 thr/row; 1 float4 each)
    const int cf  = tid & 7;
    const int qr  = tid >> 2;   // q row 0..63 (4 thr/row; 2 float4 each)
    const int qf0 = tid & 3;
    const int ti_ = tid >> 4;   // 16 i-groups x 2 rows
    const int tj_ = tid & 15;   // 16 j-groups x 4 cols

    const float4* ctx4 = (const float4*)(ctx + ((size_t)b * LC + i0) * DD);
    const float4* q4   = (const float4*)(qst + (size_t)b * LQ * DD);

    const uint32_t sc_dst =
        (uint32_t)__cvta_generic_to_shared(&sC[0][cr][cf * 4]);
    const uint32_t stage_bytes = TI * SCS * 4;

    // prologue: 3 ctx chunks in flight
#pragma unroll
    for (int st = 0; st < 3; st++) {
        cp16(sc_dst + st * stage_bytes, &ctx4[(size_t)cr * 64 + st * 8 + cf]);
        cp_commit();
    }
    // q chunk 0 -> regs
    float4 qd[2];
#pragma unroll
    for (int k = 0; k < 2; k++) qd[k] = __ldg(&q4[(size_t)qr * 64 + qf0 + 4 * k]);

    float sc_p = 0.f, c1_p = 0.f, sq_p = 0.f, q1_p = 0.f;
    float acc[2][4];
#pragma unroll
    for (int a = 0; a < 2; a++)
#pragma unroll
        for (int e = 0; e < 4; e++) acc[a][e] = 0.f;

    cp_wait2();          // chunk 0 resident
    __syncthreads();     // ctx0 + weights visible

    // process q chunk 0 -> sQT[0]  (premultiplied by w_p)
#pragma unroll
    for (int k = 0; k < 2; k++) {
        int dl = (qf0 + 4 * k) * 4, dg = dl;
        float4 v = qd[k];
        float4 wqv = *(const float4*)&sw[3 * DD + dg];
        float4 wmv = *(const float4*)&sw[4 * DD + dg];
        float4 wpv = *(const float4*)&sw[2 * DD + dg];
        sq_p += v.x * wqv.x + v.y * wqv.y + v.z * wqv.z + v.w * wqv.w;
        q1_p += v.x * wmv.x + v.y * wmv.y + v.z * wmv.z + v.w * wmv.w;
        sQT[0][dl + 0][qr] = v.x * wpv.x;
        sQT[0][dl + 1][qr] = v.y * wpv.y;
        sQT[0][dl + 2][qr] = v.z * wpv.z;
        sQT[0][dl + 3][qr] = v.w * wpv.w;
    }
    __syncthreads();

#pragma unroll 1
    for (int c = 0; c < CH; c++) {
        const int st  = c & 3;
        const int qb  = c & 1;
        // keep 3 ctx chunks in flight (empty group at tail keeps count exact)
        if (c + 3 < CH)
            cp16(sc_dst + ((c + 3) & 3) * stage_bytes,
                 &ctx4[(size_t)cr * 64 + (c + 3) * 8 + cf]);
        cp_commit();
        // q prefetch chunk c+1
        if (c + 1 < CH)
#pragma unroll
            for (int k = 0; k < 2; k++)
                qd[k] = __ldg(&q4[(size_t)qr * 64 + (c + 1) * 8 + qf0 + 4 * k]);

        // ---- GEMM with explicit register double-buffering ----
        {
            float4 cva[2], qva[4], cvb[2], qvb[4];
#pragma unroll
            for (int a = 0; a < 2; a++) cva[a] = *(const float4*)&sC[st][ti_ * 2 + a][0];
#pragma unroll
            for (int dd = 0; dd < 4; dd++) qva[dd] = *(const float4*)&sQT[qb][dd][tj_ * 4];
#pragma unroll
            for (int s = 0; s < 8; s++) {
                const int d = s * 4;
                float4* cvc = (s & 1) ? cvb : cva;
                float4* qvc = (s & 1) ? qvb : qva;
                float4* cvn = (s & 1) ? cva : cvb;
                float4* qvn = (s & 1) ? qva : qvb;
                if (s < 7) {
#pragma unroll
                    for (int a = 0; a < 2; a++)
                        cvn[a] = *(const float4*)&sC[st][ti_ * 2 + a][d + 4];
#pragma unroll
                    for (int dd = 0; dd < 4; dd++)
                        qvn[dd] = *(const float4*)&sQT[qb][d + 4 + dd][tj_ * 4];
                }
#pragma unroll
                for (int a = 0; a < 2; a++) {
                    const float cx = cvc[a].x, cy = cvc[a].y,
                                cz = cvc[a].z, cw = cvc[a].w;
#pragma unroll
                    for (int e = 0; e < 4; e++) {
                        acc[a][e] += cx * ((const float*)&qvc[0])[e]
                                   + cy * ((const float*)&qvc[1])[e]
                                   + cz * ((const float*)&qvc[2])[e]
                                   + cw * ((const float*)&qvc[3])[e];
                    }
                }
            }
        }

        // ---- sc / ctx1 row-dot partials from raw ctx in smem ----
        {
            int dl = cf * 4, dg = c * W + dl;
            float4 v   = *(const float4*)&sC[st][cr][dl];
            float4 wcv = *(const float4*)&sw[dg];
            float4 wiv = *(const float4*)&sw[DD + dg];
            sc_p += v.x * wcv.x + v.y * wcv.y + v.z * wcv.z + v.w * wcv.w;
            c1_p += v.x * wiv.x + v.y * wiv.y + v.z * wiv.z + v.w * wiv.w;
        }

        // ---- process q chunk c+1 into other sQT buffer ----
        if (c + 1 < CH) {
            const int nb = qb ^ 1;
            const int cg = (c + 1) * W;
#pragma unroll
            for (int k = 0; k < 2; k++) {
                int dl = (qf0 + 4 * k) * 4, dg = cg + dl;
                float4 v = qd[k];
                float4 wqv = *(const float4*)&sw[3 * DD + dg];
                float4 wmv = *(const float4*)&sw[4 * DD + dg];
                float4 wpv = *(const float4*)&sw[2 * DD + dg];
                sq_p += v.x * wqv.x + v.y * wqv.y + v.z * wqv.z + v.w * wqv.w;
                q1_p += v.x * wmv.x + v.y * wmv.y + v.z * wmv.z + v.w * wmv.w;
                sQT[nb][dl + 0][qr] = v.x * wpv.x;
                sQT[nb][dl + 1][qr] = v.y * wpv.y;
                sQT[nb][dl + 2][qr] = v.z * wpv.z;
                sQT[nb][dl + 3][qr] = v.w * wpv.w;
            }
        }

        cp_wait2();        // chunk c+1 resident in smem
        __syncthreads();
    }

    // ---- reduce fused row-dot partials ----
    sc_p += __shfl_xor_sync(0xffffffffu, sc_p, 1);
    sc_p += __shfl_xor_sync(0xffffffffu, sc_p, 2);
    sc_p += __shfl_xor_sync(0xffffffffu, sc_p, 4);
    c1_p += __shfl_xor_sync(0xffffffffu, c1_p, 1);
    c1_p += __shfl_xor_sync(0xffffffffu, c1_p, 2);
    c1_p += __shfl_xor_sync(0xffffffffu, c1_p, 4);
    if (cf == 0) { s_sc[cr] = sc_p; s_c1[cr] = c1_p; }
    sq_p += __shfl_xor_sync(0xffffffffu, sq_p, 1);
    sq_p += __shfl_xor_sync(0xffffffffu, sq_p, 2);
    q1_p += __shfl_xor_sync(0xffffffffu, q1_p, 1);
    q1_p += __shfl_xor_sync(0xffffffffu, q1_p, 2);
    if (qf0 == 0) { s_sq[qr] = sq_p; s_q1[qr] = q1_p; }
    __syncthreads();

    const float bias = att_b[0];
    float myq1[4], addj[4];
#pragma unroll
    for (int e = 0; e < 4; e++) {
        int j = tj_ * 4 + e;
        myq1[e] = s_q1[j];
        addj[e] = s_sq[j] + s_pen[j] + bias;
    }

    // ---- per-row softmax over j ----
#pragma unroll
    for (int a = 0; a < 2; a++) {
        int i = ti_ * 2 + a;
        float sci = s_sc[i];
        float l[4], mx = -INFINITY;
#pragma unroll
        for (int e = 0; e < 4; e++) {
            l[e] = acc[a][e] + sci + addj[e];
            mx = fmaxf(mx, l[e]);
        }
#pragma unroll
        for (int s = 1; s < 16; s <<= 1)
            mx = fmaxf(mx, __shfl_xor_sync(0xffffffffu, mx, s));
        float num = 0.f, den = 0.f;
#pragma unroll
        for (int e = 0; e < 4; e++) {
            float ev = __expf(l[e] - mx);
            num += ev * myq1[e];
            den += ev;
        }
#pragma unroll
        for (int s = 1; s < 16; s <<= 1) {
            num += __shfl_xor_sync(0xffffffffu, num, s);
            den += __shfl_xor_sync(0xffffffffu, den, s);
        }
        if (tj_ == 0) {
            int gi = b * LC + i0 + i;
            g_U[gi]    = num / den;
            g_m[gi]    = mx;
            g_ctx1[gi] = s_c1[i];
        }
    }

    // ---- fused finalization ----
    __threadfence();
    __syncthreads();
    if (tid == 0) s_last = (atomicAdd(&g_cnt[b], 1u) == (LC / TI) - 1u) ? 1u : 0u;
    __syncthreads();
    if (!s_last) return;
    __threadfence();   // acquire side

    const int wid = tid >> 5, lid = tid & 31;
    float m[2], c1[2];
#pragma unroll
    for (int k = 0; k < 2; k++) {
        int idx = tid + NT * k;
        m[k]  = __ldcg(&g_m[b * LC + idx]);
        c1[k] = __ldcg(&g_ctx1[b * LC + idx]);
    }
    float mx = fmaxf(m[0], m[1]);
#pragma unroll
    for (int s = 16; s > 0; s >>= 1)
        mx = fmaxf(mx, __shfl_xor_sync(0xffffffffu, mx, s));
    if (lid == 0) s_red[wid] = mx;
    __syncthreads();
    float M = s_red[0];
#pragma unroll
    for (int w = 1; w < 8; w++) M = fmaxf(M, s_red[w]);
    __syncthreads();

    float den = 0.f, num = 0.f;
#pragma unroll
    for (int k = 0; k < 2; k++) {
        float ev = __expf(m[k] - M);
        den += ev;
        num += ev * c1[k];
    }
#pragma unroll
    for (int s = 16; s > 0; s >>= 1) {
        den += __shfl_xor_sync(0xffffffffu, den, s);
        num += __shfl_xor_sync(0xffffffffu, num, s);
    }
    if (lid == 0) { s_red[8 + wid] = den; s_red[16 + wid] = num; }
    __syncthreads();
    float DEN = 0.f, NUM = 0.f;
#pragma unroll
    for (int w = 0; w < 8; w++) { DEN += s_red[8 + w]; NUM += s_red[16 + w]; }
    float H = NUM / DEN;

#pragma unroll
    for (int k = 0; k < 2; k++) {
        int idx = tid + NT * k;
        float u = __ldcg(&g_U[b * LC + idx]);
        ((float4*)out)[(size_t)b * LC + idx] = make_float4(c1[k], u, c1[k] * u, u * H);
    }
    if (tid == 0) g_cnt[b] = 0;   // reset for next graph replay
}

extern "C" void kernel_launch(void* const* d_in, const int* in_sizes, int n_in,
                              void* d_out, int out_size)
{
    const float* ctx   = (const float*)d_in[0];  // (8,512,256)
    const float* qst   = (const float*)d_in[1];  // (8,64,256)
    const int*   mask  = (const int*)d_in[2];    // (8,64)
    const float* att_w = (const float*)d_in[3];  // (768,)
    const float* att_b = (const float*)d_in[4];  // (1,)
    const float* w_in  = (const float*)d_in[5];  // (256,)
    const float* w_mem = (const float*)d_in[6];  // (256,)
    float* out = (float*)d_out;                  // (8,512,4)

    dim3 grid(LC / TI, BB);
    bi_attn_fused<<<grid, NT>>>(ctx, qst, mask, att_w, att_b, w_in, w_mem, out);
}

// round 9
// speedup vs baseline: 1.1364x; 1.1364x over previous
#include <cuda_runtime.h>
#include <cstdint>
#include <math.h>

#define BB 8
#define LC 512
#define LQ 64
#define DD 256
#define TI 32
#define NT 256
#define SQS 68                  // sQT row stride (words), conflict-free
#define NEG_BIG 1e30f

// dynamic smem layout (float offsets)
#define OFF_SC  0                               // raw ctx tile [TI][DD] (no pad: broadcast reads)
#define OFF_SQT (TI * DD)                       // (w_p*q)^T [DD][SQS]
#define OFF_SW  (OFF_SQT + DD * SQS)            // wc | w_in | wp | wq | w_mem
#define DYN_FLOATS (OFF_SW + 5 * DD)
#define DYN_BYTES  (DYN_FLOATS * 4)             // 107,520 B

__device__ float g_ctx1[BB * LC];
__device__ float g_U[BB * LC];
__device__ float g_m[BB * LC];
__device__ unsigned int g_cnt[BB];

__global__ __launch_bounds__(NT) void bi_attn_fused(
    const float* __restrict__ ctx, const float* __restrict__ qst,
    const int* __restrict__ mask, const float* __restrict__ att_w,
    const float* __restrict__ att_b, const float* __restrict__ w_in,
    const float* __restrict__ w_mem, float* __restrict__ out)
{
    extern __shared__ __align__(128) float dsm[];
    __shared__ float s_sc[TI], s_c1[TI], s_sq[LQ], s_q1[LQ], s_pen[LQ];
    __shared__ float s_red[24];
    __shared__ unsigned s_last;
    __shared__ __align__(8) unsigned long long s_mbar;

    const int b   = blockIdx.y;
    const int i0  = blockIdx.x * TI;
    const int tid = threadIdx.x;

    // ---- producer: one bulk copy of the whole ctx tile (32 KB, contiguous) ----
    if (tid == 0) {
        uint32_t mb = (uint32_t)__cvta_generic_to_shared(&s_mbar);
        asm volatile("mbarrier.init.shared.b64 [%0], %1;" :: "r"(mb), "r"(1));
        asm volatile("fence.proxy.async.shared::cta;" ::: "memory");
        asm volatile("mbarrier.arrive.expect_tx.shared.b64 _, [%0], %1;"
                     :: "r"(mb), "r"((unsigned)(TI * DD * 4)));
        uint32_t dst = (uint32_t)__cvta_generic_to_shared(&dsm[OFF_SC]);
        const float* src = ctx + ((size_t)b * LC + i0) * DD;
        asm volatile(
            "cp.async.bulk.shared::cta.global.mbarrier::complete_tx::bytes "
            "[%0], [%1], %2, [%3];"
            :: "r"(dst), "l"(src), "r"((unsigned)(TI * DD * 4)), "r"(mb)
            : "memory");
    }

    // ---- weights -> smem ----
    for (int i = tid; i < 5 * DD; i += NT) {
        float v;
        if      (i < DD)      v = att_w[i];             // wc
        else if (i < 2 * DD)  v = w_in[i - DD];         // w_in
        else if (i < 3 * DD)  v = att_w[i];             // wp = att_w[512..768)
        else if (i < 4 * DD)  v = att_w[i - 2 * DD];    // wq = att_w[256..512)
        else                  v = w_mem[i - 4 * DD];    // w_mem
        dsm[OFF_SW + i] = v;
    }
    if (tid < LQ) {
        float mf = (float)mask[b * LQ + tid];
        s_pen[tid] = -NEG_BIG * (1.0f - mf);
    }
    __syncthreads();   // weights visible (needed by q processing below)

    // ---- build sQT = (w_p * q)^T, fused sq/q1 row dots ----
    const int qr  = tid >> 2;    // q row 0..63 (4 thr/row)
    const int qf0 = tid & 3;     // 16 float4 per thread: f = qf0 + 4k
    const float4* q4 = (const float4*)(qst + (size_t)b * LQ * DD);

    float sq_p = 0.f, q1_p = 0.f;
#pragma unroll
    for (int k = 0; k < 16; k++) {
        const int f  = qf0 + 4 * k;
        const int dg = f * 4;
        float4 v   = __ldg(&q4[(size_t)qr * 64 + f]);
        float4 wqv = *(const float4*)&dsm[OFF_SW + 3 * DD + dg];
        float4 wmv = *(const float4*)&dsm[OFF_SW + 4 * DD + dg];
        float4 wpv = *(const float4*)&dsm[OFF_SW + 2 * DD + dg];
        sq_p += v.x * wqv.x + v.y * wqv.y + v.z * wqv.z + v.w * wqv.w;
        q1_p += v.x * wmv.x + v.y * wmv.y + v.z * wmv.z + v.w * wmv.w;
        dsm[OFF_SQT + (dg + 0) * SQS + qr] = v.x * wpv.x;
        dsm[OFF_SQT + (dg + 1) * SQS + qr] = v.y * wpv.y;
        dsm[OFF_SQT + (dg + 2) * SQS + qr] = v.z * wpv.z;
        dsm[OFF_SQT + (dg + 3) * SQS + qr] = v.w * wpv.w;
    }
    sq_p += __shfl_xor_sync(0xffffffffu, sq_p, 1);
    sq_p += __shfl_xor_sync(0xffffffffu, sq_p, 2);
    q1_p += __shfl_xor_sync(0xffffffffu, q1_p, 1);
    q1_p += __shfl_xor_sync(0xffffffffu, q1_p, 2);
    if (qf0 == 0) { s_sq[qr] = sq_p; s_q1[qr] = q1_p; }

    __syncthreads();   // sQT + s_sq/s_q1 visible; ONLY barrier before epilogue

    // ---- wait for ctx bulk copy (likely already complete) ----
    {
        uint32_t mb = (uint32_t)__cvta_generic_to_shared(&s_mbar);
        uint32_t done;
        asm volatile(
            "{\n\t.reg .pred p;\n\t"
            "mbarrier.try_wait.parity.acquire.cta.shared::cta.b64 p, [%1], 0;\n\t"
            "selp.b32 %0, 1, 0, p;\n\t}"
            : "=r"(done) : "r"(mb) : "memory");
        while (!done) {
            asm volatile(
                "{\n\t.reg .pred p;\n\t"
                "mbarrier.try_wait.parity.acquire.cta.shared::cta.b64 p, [%1], 0, 0x989680;\n\t"
                "selp.b32 %0, 1, 0, p;\n\t}"
                : "=r"(done) : "r"(mb) : "memory");
        }
    }

    // ---- free-running GEMM + ctx row dots: NO barriers until epilogue ----
    const int cr  = tid >> 3;    // ctx row 0..31 (8 thr/row) for row dots
    const int cf  = tid & 7;
    const int ti_ = tid >> 4;    // 16 i-groups x 2 rows
    const int tj_ = tid & 15;    // 16 j-groups x 4 cols

    float sc_p = 0.f, c1_p = 0.f;
    float acc[2][4];
#pragma unroll
    for (int a = 0; a < 2; a++)
#pragma unroll
        for (int e = 0; e < 4; e++) acc[a][e] = 0.f;

    const float* sCr0 = &dsm[OFF_SC + (ti_ * 2 + 0) * DD];
    const float* sCr1 = &dsm[OFF_SC + (ti_ * 2 + 1) * DD];
    const float* sQb  = &dsm[OFF_SQT + tj_ * 4];

#pragma unroll 1
    for (int c = 0; c < 8; c++) {
        const int c0 = c * 32;
        // register-double-buffered inner loop over 32 d's
        float4 cva[2], qva[4], cvb[2], qvb[4];
        cva[0] = *(const float4*)&sCr0[c0];
        cva[1] = *(const float4*)&sCr1[c0];
#pragma unroll
        for (int dd = 0; dd < 4; dd++)
            qva[dd] = *(const float4*)&sQb[(c0 + dd) * SQS];
#pragma unroll
        for (int s = 0; s < 8; s++) {
            const int d = c0 + s * 4;
            float4* cvc = (s & 1) ? cvb : cva;
            float4* qvc = (s & 1) ? qvb : qva;
            float4* cvn = (s & 1) ? cva : cvb;
            float4* qvn = (s & 1) ? qva : qvb;
            if (s < 7) {
                cvn[0] = *(const float4*)&sCr0[d + 4];
                cvn[1] = *(const float4*)&sCr1[d + 4];
#pragma unroll
                for (int dd = 0; dd < 4; dd++)
                    qvn[dd] = *(const float4*)&sQb[(d + 4 + dd) * SQS];
            }
#pragma unroll
            for (int a = 0; a < 2; a++) {
                const float cx = cvc[a].x, cy = cvc[a].y,
                            cz = cvc[a].z, cw = cvc[a].w;
#pragma unroll
                for (int e = 0; e < 4; e++) {
                    acc[a][e] += cx * ((const float*)&qvc[0])[e]
                               + cy * ((const float*)&qvc[1])[e]
                               + cz * ((const float*)&qvc[2])[e]
                               + cw * ((const float*)&qvc[3])[e];
                }
            }
        }
        // ctx row-dot partials for this chunk
        {
            const int dg = c0 + cf * 4;
            float4 v   = *(const float4*)&dsm[OFF_SC + cr * DD + dg];
            float4 wcv = *(const float4*)&dsm[OFF_SW + dg];
            float4 wiv = *(const float4*)&dsm[OFF_SW + DD + dg];
            sc_p += v.x * wcv.x + v.y * wcv.y + v.z * wcv.z + v.w * wcv.w;
            c1_p += v.x * wiv.x + v.y * wiv.y + v.z * wiv.z + v.w * wiv.w;
        }
    }

    // ---- reduce ctx row-dot partials ----
    sc_p += __shfl_xor_sync(0xffffffffu, sc_p, 1);
    sc_p += __shfl_xor_sync(0xffffffffu, sc_p, 2);
    sc_p += __shfl_xor_sync(0xffffffffu, sc_p, 4);
    c1_p += __shfl_xor_sync(0xffffffffu, c1_p, 1);
    c1_p += __shfl_xor_sync(0xffffffffu, c1_p, 2);
    c1_p += __shfl_xor_sync(0xffffffffu, c1_p, 4);
    if (cf == 0) { s_sc[cr] = sc_p; s_c1[cr] = c1_p; }
    __syncthreads();

    const float bias = att_b[0];
    float myq1[4], addj[4];
#pragma unroll
    for (int e = 0; e < 4; e++) {
        int j = tj_ * 4 + e;
        myq1[e] = s_q1[j];
        addj[e] = s_sq[j] + s_pen[j] + bias;
    }

    // ---- per-row softmax over j ----
#pragma unroll
    for (int a = 0; a < 2; a++) {
        int i = ti_ * 2 + a;
        float sci = s_sc[i];
        float l[4], mx = -INFINITY;
#pragma unroll
        for (int e = 0; e < 4; e++) {
            l[e] = acc[a][e] + sci + addj[e];
            mx = fmaxf(mx, l[e]);
        }
#pragma unroll
        for (int s = 1; s < 16; s <<= 1)
            mx = fmaxf(mx, __shfl_xor_sync(0xffffffffu, mx, s));
        float num = 0.f, den = 0.f;
#pragma unroll
        for (int e = 0; e < 4; e++) {
            float ev = __expf(l[e] - mx);
            num += ev * myq1[e];
            den += ev;
        }
#pragma unroll
        for (int s = 1; s < 16; s <<= 1) {
            num += __shfl_xor_sync(0xffffffffu, num, s);
            den += __shfl_xor_sync(0xffffffffu, den, s);
        }
        if (tj_ == 0) {
            int gi = b * LC + i0 + i;
            g_U[gi]    = num / den;
            g_m[gi]    = mx;
            g_ctx1[gi] = s_c1[i];
        }
    }

    // ---- fused finalization: last block of this batch ----
    __threadfence();
    __syncthreads();
    if (tid == 0) s_last = (atomicAdd(&g_cnt[b], 1u) == (LC / TI) - 1u) ? 1u : 0u;
    __syncthreads();
    if (!s_last) return;
    __threadfence();   // acquire side

    const int wid = tid >> 5, lid = tid & 31;
    float m[2], c1[2];
#pragma unroll
    for (int k = 0; k < 2; k++) {
        int idx = tid + NT * k;
        m[k]  = __ldcg(&g_m[b * LC + idx]);
        c1[k] = __ldcg(&g_ctx1[b * LC + idx]);
    }
    float mx = fmaxf(m[0], m[1]);
#pragma unroll
    for (int s = 16; s > 0; s >>= 1)
        mx = fmaxf(mx, __shfl_xor_sync(0xffffffffu, mx, s));
    if (lid == 0) s_red[wid] = mx;
    __syncthreads();
    float M = s_red[0];
#pragma unroll
    for (int w = 1; w < 8; w++) M = fmaxf(M, s_red[w]);
    __syncthreads();

    float den = 0.f, num = 0.f;
#pragma unroll
    for (int k = 0; k < 2; k++) {
        float ev = __expf(m[k] - M);
        den += ev;
        num += ev * c1[k];
    }
#pragma unroll
    for (int s = 16; s > 0; s >>= 1) {
        den += __shfl_xor_sync(0xffffffffu, den, s);
        num += __shfl_xor_sync(0xffffffffu, num, s);
    }
    if (lid == 0) { s_red[8 + wid] = den; s_red[16 + wid] = num; }
    __syncthreads();
    float DEN = 0.f, NUM = 0.f;
#pragma unroll
    for (int w = 0; w < 8; w++) { DEN += s_red[8 + w]; NUM += s_red[16 + w]; }
    float H = NUM / DEN;

#pragma unroll
    for (int k = 0; k < 2; k++) {
        int idx = tid + NT * k;
        float u = __ldcg(&g_U[b * LC + idx]);
        ((float4*)out)[(size_t)b * LC + idx] = make_float4(c1[k], u, c1[k] * u, u * H);
    }
    if (tid == 0) g_cnt[b] = 0;   // reset for next graph replay
}

extern "C" void kernel_launch(void* const* d_in, const int* in_sizes, int n_in,
                              void* d_out, int out_size)
{
    const float* ctx   = (const float*)d_in[0];  // (8,512,256)
    const float* qst   = (const float*)d_in[1];  // (8,64,256)
    const int*   mask  = (const int*)d_in[2];    // (8,64)
    const float* att_w = (const float*)d_in[3];  // (768,)
    const float* att_b = (const float*)d_in[4];  // (1,)
    const float* w_in  = (const float*)d_in[5];  // (256,)
    const float* w_mem = (const float*)d_in[6];  // (256,)
    float* out = (float*)d_out;                  // (8,512,4)

    cudaFuncSetAttribute(bi_attn_fused,
                         cudaFuncAttributeMaxDynamicSharedMemorySize, DYN_BYTES);
    dim3 grid(LC / TI, BB);
    bi_attn_fused<<<grid, NT, DYN_BYTES>>>(ctx, qst, mask, att_w, att_b,
                                           w_in, w_mem, out);
}

// round 11
// speedup vs baseline: 1.1650x; 1.0252x over previous
#include <cuda_runtime.h>
#include <cstdint>
#include <math.h>

#define BB 8
#define LC 512
#define LQ 64
#define DD 256
#define TI 32
#define NT 256
#define SA 260                  // hi/lo tile row stride (words): conflict-free frag loads
#define SS 68                   // S tile row stride
#define NEG_BIG 1e30f

// dynamic smem layout (float offsets)
#define OFF_CH 0                          // ctx hi  [32][SA]
#define OFF_CL (OFF_CH + TI * SA)         // ctx lo
#define OFF_QH (OFF_CL + TI * SA)         // (wp*q) hi [64][SA]
#define OFF_QL (OFF_QH + LQ * SA)         // (wp*q) lo
#define OFF_S  (OFF_QL + LQ * SA)         // S [32][SS]
#define OFF_W  (OFF_S + TI * SS)          // wc | w_in | wp | wq | w_mem
#define DYN_FLOATS (OFF_W + 5 * DD)
#define DYN_BYTES  (DYN_FLOATS * 4)       // ~213.5 KB

__device__ float g_ctx1[BB * LC];
__device__ float g_U[BB * LC];
__device__ float g_m[BB * LC];
__device__ unsigned int g_cnt[BB];

__device__ __forceinline__ float tf32r(float x) {
    float r;
    asm("cvt.rna.tf32.f32 %0, %1;" : "=f"(r) : "f"(x));
    return r;
}
__device__ __forceinline__ void mma8(float* d, const uint32_t* a, const uint32_t* bb) {
    asm volatile(
        "mma.sync.aligned.m16n8k8.row.col.f32.tf32.tf32.f32 "
        "{%0,%1,%2,%3}, {%4,%5,%6,%7}, {%8,%9}, {%0,%1,%2,%3};"
        : "+f"(d[0]), "+f"(d[1]), "+f"(d[2]), "+f"(d[3])
        : "r"(a[0]), "r"(a[1]), "r"(a[2]), "r"(a[3]), "r"(bb[0]), "r"(bb[1]));
}

__global__ __launch_bounds__(NT) void bi_attn_fused(
    const float* __restrict__ ctx, const float* __restrict__ qst,
    const int* __restrict__ mask, const float* __restrict__ att_w,
    const float* __restrict__ att_b, const float* __restrict__ w_in,
    const float* __restrict__ w_mem, float* __restrict__ out)
{
    extern __shared__ __align__(128) float dsm[];
    __shared__ float s_sc[TI], s_c1[TI], s_sq[LQ], s_q1[LQ], s_pen[LQ];
    __shared__ float s_red[24];
    __shared__ unsigned s_last;

    const int b   = blockIdx.y;
    const int i0  = blockIdx.x * TI;
    const int tid = threadIdx.x;

    const float4* ctx4 = (const float4*)(ctx + ((size_t)b * LC + i0) * DD);
    const float4* q4   = (const float4*)(qst + (size_t)b * LQ * DD);

    // mappings
    const int cr  = tid >> 3, cf  = tid & 7;   // ctx: 32 rows x 8 thr (f = cf + 8k)
    const int qr  = tid >> 2, qf0 = tid & 3;   // q:   64 rows x 4 thr (f = qf0 + 4k)

    // ---- issue ctx + q LDGs early (no dependencies) ----
    float4 cv[8];
#pragma unroll
    for (int k = 0; k < 8; k++) cv[k] = __ldg(&ctx4[(size_t)cr * 64 + cf + 8 * k]);
    float4 qv[16];
#pragma unroll
    for (int k = 0; k < 16; k++) qv[k] = __ldg(&q4[(size_t)qr * 64 + qf0 + 4 * k]);

    // ---- weights -> smem ----
    for (int i = tid; i < 5 * DD; i += NT) {
        float v;
        if      (i < DD)      v = att_w[i];             // wc
        else if (i < 2 * DD)  v = w_in[i - DD];         // w_in
        else if (i < 3 * DD)  v = att_w[i];             // wp = att_w[512..768)
        else if (i < 4 * DD)  v = att_w[i - 2 * DD];    // wq = att_w[256..512)
        else                  v = w_mem[i - 4 * DD];    // w_mem
        dsm[OFF_W + i] = v;
    }
    if (tid < LQ) {
        float mf = (float)mask[b * LQ + tid];
        s_pen[tid] = -NEG_BIG * (1.0f - mf);
    }
    __syncthreads();   // weights visible

    // ---- ctx staging: dots + tf32 hi/lo split ----
    float sc_p = 0.f, c1_p = 0.f;
#pragma unroll
    for (int k = 0; k < 8; k++) {
        const int f  = cf + 8 * k;
        const int dg = f * 4;
        float4 v   = cv[k];
        float4 wcv = *(const float4*)&dsm[OFF_W + dg];
        float4 wiv = *(const float4*)&dsm[OFF_W + DD + dg];
        sc_p += v.x * wcv.x + v.y * wcv.y + v.z * wcv.z + v.w * wcv.w;
        c1_p += v.x * wiv.x + v.y * wiv.y + v.z * wiv.z + v.w * wiv.w;
        float4 h, l;
        h.x = tf32r(v.x); l.x = tf32r(v.x - h.x);
        h.y = tf32r(v.y); l.y = tf32r(v.y - h.y);
        h.z = tf32r(v.z); l.z = tf32r(v.z - h.z);
        h.w = tf32r(v.w); l.w = tf32r(v.w - h.w);
        *(float4*)&dsm[OFF_CH + cr * SA + dg] = h;
        *(float4*)&dsm[OFF_CL + cr * SA + dg] = l;
    }
    sc_p += __shfl_xor_sync(0xffffffffu, sc_p, 1);
    sc_p += __shfl_xor_sync(0xffffffffu, sc_p, 2);
    sc_p += __shfl_xor_sync(0xffffffffu, sc_p, 4);
    c1_p += __shfl_xor_sync(0xffffffffu, c1_p, 1);
    c1_p += __shfl_xor_sync(0xffffffffu, c1_p, 2);
    c1_p += __shfl_xor_sync(0xffffffffu, c1_p, 4);
    if (cf == 0) { s_sc[cr] = sc_p; s_c1[cr] = c1_p; }

    // ---- q staging: dots, wp-premul, tf32 hi/lo split ----
    float sq_p = 0.f, q1_p = 0.f;
#pragma unroll
    for (int k = 0; k < 16; k++) {
        const int f  = qf0 + 4 * k;
        const int dg = f * 4;
        float4 v   = qv[k];
        float4 wqv = *(const float4*)&dsm[OFF_W + 3 * DD + dg];
        float4 wmv = *(const float4*)&dsm[OFF_W + 4 * DD + dg];
        float4 wpv = *(const float4*)&dsm[OFF_W + 2 * DD + dg];
        sq_p += v.x * wqv.x + v.y * wqv.y + v.z * wqv.z + v.w * wqv.w;
        q1_p += v.x * wmv.x + v.y * wmv.y + v.z * wmv.z + v.w * wmv.w;
        float4 y = make_float4(v.x * wpv.x, v.y * wpv.y, v.z * wpv.z, v.w * wpv.w);
        float4 h, l;
        h.x = tf32r(y.x); l.x = tf32r(y.x - h.x);
        h.y = tf32r(y.y); l.y = tf32r(y.y - h.y);
        h.z = tf32r(y.z); l.z = tf32r(y.z - h.z);
        h.w = tf32r(y.w); l.w = tf32r(y.w - h.w);
        *(float4*)&dsm[OFF_QH + qr * SA + dg] = h;
        *(float4*)&dsm[OFF_QL + qr * SA + dg] = l;
    }
    sq_p += __shfl_xor_sync(0xffffffffu, sq_p, 1);
    sq_p += __shfl_xor_sync(0xffffffffu, sq_p, 2);
    q1_p += __shfl_xor_sync(0xffffffffu, q1_p, 1);
    q1_p += __shfl_xor_sync(0xffffffffu, q1_p, 2);
    if (qf0 == 0) { s_sq[qr] = sq_p; s_q1[qr] = q1_p; }
    __syncthreads();   // hi/lo tiles + row dots visible

    // ---- tensor-core GEMM: warp w -> m-tile (w>>2)*16, n-strips (w&3)*16+{0,8} ----
    {
        const int warp = tid >> 5, lid = tid & 31;
        const int g = lid >> 2, t = lid & 3;
        const int m  = (warp >> 2) * 16;
        const int n0 = (warp & 3) * 16;
        const uint32_t* Ch = (const uint32_t*)&dsm[OFF_CH];
        const uint32_t* Cl = (const uint32_t*)&dsm[OFF_CL];
        const uint32_t* Qh = (const uint32_t*)&dsm[OFF_QH];
        const uint32_t* Ql = (const uint32_t*)&dsm[OFF_QL];
        const int ra = (m + g) * SA, rb = (m + g + 8) * SA;
        const int nb0 = (n0 + g) * SA, nb1 = (n0 + 8 + g) * SA;

        float d0[2][4] = {}, d1[2][4] = {};   // hh and cross accumulators
#pragma unroll 4
        for (int k0 = 0; k0 < DD; k0 += 8) {
            uint32_t ah[4], al[4], bh[2][2], bl[2][2];
            ah[0] = Ch[ra + k0 + t];     ah[1] = Ch[rb + k0 + t];
            ah[2] = Ch[ra + k0 + t + 4]; ah[3] = Ch[rb + k0 + t + 4];
            al[0] = Cl[ra + k0 + t];     al[1] = Cl[rb + k0 + t];
            al[2] = Cl[ra + k0 + t + 4]; al[3] = Cl[rb + k0 + t + 4];
            bh[0][0] = Qh[nb0 + k0 + t]; bh[0][1] = Qh[nb0 + k0 + t + 4];
            bh[1][0] = Qh[nb1 + k0 + t]; bh[1][1] = Qh[nb1 + k0 + t + 4];
            bl[0][0] = Ql[nb0 + k0 + t]; bl[0][1] = Ql[nb0 + k0 + t + 4];
            bl[1][0] = Ql[nb1 + k0 + t]; bl[1][1] = Ql[nb1 + k0 + t + 4];
#pragma unroll
            for (int s = 0; s < 2; s++) {
                mma8(d0[s], ah, bh[s]);   // hi*hi
                mma8(d1[s], ah, bl[s]);   // hi*lo
                mma8(d1[s], al, bh[s]);   // lo*hi
            }
        }
        // store S fragments (c-layout: (g,2t),(g,2t+1),(g+8,2t),(g+8,2t+1))
#pragma unroll
        for (int s = 0; s < 2; s++) {
            const int nc = n0 + 8 * s + 2 * t;
            *(float2*)&dsm[OFF_S + (m + g) * SS + nc] =
                make_float2(d0[s][0] + d1[s][0], d0[s][1] + d1[s][1]);
            *(float2*)&dsm[OFF_S + (m + g + 8) * SS + nc] =
                make_float2(d0[s][2] + d1[s][2], d0[s][3] + d1[s][3]);
        }
    }
    __syncthreads();   // S visible

    // ---- softmax over j (same scheme as before, logits from smem S) ----
    const int ti_ = tid >> 4;
    const int tj_ = tid & 15;
    const float bias = att_b[0];
    float myq1[4], addj[4];
#pragma unroll
    for (int e = 0; e < 4; e++) {
        int j = tj_ * 4 + e;
        myq1[e] = s_q1[j];
        addj[e] = s_sq[j] + s_pen[j] + bias;
    }
#pragma unroll
    for (int a = 0; a < 2; a++) {
        int i = ti_ * 2 + a;
        float sci = s_sc[i];
        float4 sv = *(const float4*)&dsm[OFF_S + i * SS + tj_ * 4];
        float l[4], mx = -INFINITY;
        l[0] = sv.x + sci + addj[0];
        l[1] = sv.y + sci + addj[1];
        l[2] = sv.z + sci + addj[2];
        l[3] = sv.w + sci + addj[3];
#pragma unroll
        for (int e = 0; e < 4; e++) mx = fmaxf(mx, l[e]);
#pragma unroll
        for (int s = 1; s < 16; s <<= 1)
            mx = fmaxf(mx, __shfl_xor_sync(0xffffffffu, mx, s));
        float num = 0.f, den = 0.f;
#pragma unroll
        for (int e = 0; e < 4; e++) {
            float ev = __expf(l[e] - mx);
            num += ev * myq1[e];
            den += ev;
        }
#pragma unroll
        for (int s = 1; s < 16; s <<= 1) {
            num += __shfl_xor_sync(0xffffffffu, num, s);
            den += __shfl_xor_sync(0xffffffffu, den, s);
        }
        if (tj_ == 0) {
            int gi = b * LC + i0 + i;
            g_U[gi]    = num / den;
            g_m[gi]    = mx;
            g_ctx1[gi] = s_c1[i];
        }
    }

    // ---- fused finalization: last block of this batch ----
    __threadfence();
    __syncthreads();
    if (tid == 0) s_last = (atomicAdd(&g_cnt[b], 1u) == (LC / TI) - 1u) ? 1u : 0u;
    __syncthreads();
    if (!s_last) return;
    __threadfence();   // acquire side

    const int wid = tid >> 5, lid = tid & 31;
    float m[2], c1[2];
#pragma unroll
    for (int k = 0; k < 2; k++) {
        int idx = tid + NT * k;
        m[k]  = __ldcg(&g_m[b * LC + idx]);
        c1[k] = __ldcg(&g_ctx1[b * LC + idx]);
    }
    float mx = fmaxf(m[0], m[1]);
#pragma unroll
    for (int s = 16; s > 0; s >>= 1)
        mx = fmaxf(mx, __shfl_xor_sync(0xffffffffu, mx, s));
    if (lid == 0) s_red[wid] = mx;
    __syncthreads();
    float M = s_red[0];
#pragma unroll
    for (int w = 1; w < 8; w++) M = fmaxf(M, s_red[w]);
    __syncthreads();

    float den = 0.f, num = 0.f;
#pragma unroll
    for (int k = 0; k < 2; k++) {
        float ev = __expf(m[k] - M);
        den += ev;
        num += ev * c1[k];
    }
#pragma unroll
    for (int s = 16; s > 0; s >>= 1) {
        den += __shfl_xor_sync(0xffffffffu, den, s);
        num += __shfl_xor_sync(0xffffffffu, num, s);
    }
    if (lid == 0) { s_red[8 + wid] = den; s_red[16 + wid] = num; }
    __syncthreads();
    float DEN = 0.f, NUM = 0.f;
#pragma unroll
    for (int w = 0; w < 8; w++) { DEN += s_red[8 + w]; NUM += s_red[16 + w]; }
    float H = NUM / DEN;

#pragma unroll
    for (int k = 0; k < 2; k++) {
        int idx = tid + NT * k;
        float u = __ldcg(&g_U[b * LC + idx]);
        ((float4*)out)[(size_t)b * LC + idx] = make_float4(c1[k], u, c1[k] * u, u * H);
    }
    if (tid == 0) g_cnt[b] = 0;   // reset for next graph replay
}

extern "C" void kernel_launch(void* const* d_in, const int* in_sizes, int n_in,
                              void* d_out, int out_size)
{
    const float* ctx   = (const float*)d_in[0];  // (8,512,256)
    const float* qst   = (const float*)d_in[1];  // (8,64,256)
    const int*   mask  = (const int*)d_in[2];    // (8,64)
    const float* att_w = (const float*)d_in[3];  // (768,)
    const float* att_b = (const float*)d_in[4];  // (1,)
    const float* w_in  = (const float*)d_in[5];  // (256,)
    const float* w_mem = (const float*)d_in[6];  // (256,)
    float* out = (float*)d_out;                  // (8,512,4)

    cudaFuncSetAttribute(bi_attn_fused,
                         cudaFuncAttributeMaxDynamicSharedMemorySize, DYN_BYTES);
    dim3 grid(LC / TI, BB);
    bi_attn_fused<<<grid, NT, DYN_BYTES>>>(ctx, qst, mask, att_w, att_b,
                                           w_in, w_mem, out);
}

// round 13
// speedup vs baseline: 1.2712x; 1.0911x over previous
#include <cuda_runtime.h>
#include <cstdint>
#include <math.h>

#define BB 8
#define LC 512
#define LQ 64
#define DD 256
#define TI 32
#define NT 256
#define SA 260                  // hi/lo tile row stride (words): conflict-free frag loads
#define SS 68                   // S tile row stride
#define NEG_BIG 1e30f

// dynamic smem layout (float offsets)
#define OFF_CH 0                          // ctx hi  [32][SA]
#define OFF_CL (OFF_CH + TI * SA)         // ctx lo
#define OFF_QH (OFF_CL + TI * SA)         // (wp*q) hi [64][SA]
#define OFF_QL (OFF_QH + LQ * SA)         // (wp*q) lo
#define OFF_S  (OFF_QL + LQ * SA)         // S [32][SS]
#define DYN_FLOATS (OFF_S + TI * SS)
#define DYN_BYTES  (DYN_FLOATS * 4)

__device__ float g_U[BB * LC];
__device__ float g_part[BB * 16 * 4];     // (mloc, ploc, uloc, pad) per block
__device__ unsigned int g_cnt[BB];

__device__ __forceinline__ float tf32r(float x) {
    float r;
    asm("cvt.rna.tf32.f32 %0, %1;" : "=f"(r) : "f"(x));
    return r;
}
__device__ __forceinline__ void mma8(float* d, const uint32_t* a, const uint32_t* bb) {
    asm volatile(
        "mma.sync.aligned.m16n8k8.row.col.f32.tf32.tf32.f32 "
        "{%0,%1,%2,%3}, {%4,%5,%6,%7}, {%8,%9}, {%0,%1,%2,%3};"
        : "+f"(d[0]), "+f"(d[1]), "+f"(d[2]), "+f"(d[3])
        : "r"(a[0]), "r"(a[1]), "r"(a[2]), "r"(a[3]), "r"(bb[0]), "r"(bb[1]));
}

__global__ __launch_bounds__(NT) void bi_attn_fused(
    const float* __restrict__ ctx, const float* __restrict__ qst,
    const int* __restrict__ mask, const float* __restrict__ att_w,
    const float* __restrict__ att_b, const float* __restrict__ w_in,
    const float* __restrict__ w_mem, float* __restrict__ out)
{
    extern __shared__ __align__(128) float dsm[];
    __shared__ float s_sc[TI], s_c1[TI], s_sq[LQ], s_q1[LQ];
    __shared__ float s_m[TI], s_u[TI];
    __shared__ float s_red[4];
    __shared__ unsigned s_last;

    const int b   = blockIdx.y;
    const int i0  = blockIdx.x * TI;
    const int tid = threadIdx.x;

    const float4* ctx4 = (const float4*)(ctx + ((size_t)b * LC + i0) * DD);
    const float4* q4   = (const float4*)(qst + (size_t)b * LQ * DD);
    const float4* wc4  = (const float4*)att_w;          // [0,64)
    const float4* wq4  = wc4 + 64;                      // att_w[256..512)
    const float4* wp4  = wc4 + 128;                     // att_w[512..768)
    const float4* wi4  = (const float4*)w_in;
    const float4* wm4  = (const float4*)w_mem;

    // mappings
    const int cr  = tid >> 3, cf  = tid & 7;   // ctx: 32 rows x 8 thr (f = cf + 8k)
    const int qr  = tid >> 2, qf0 = tid & 3;   // q:   64 rows x 4 thr (f = qf0 + 4k)

    // ---- issue data LDGs immediately ----
    float4 cv[8];
#pragma unroll
    for (int k = 0; k < 8; k++) cv[k] = __ldg(&ctx4[(size_t)cr * 64 + cf + 8 * k]);
    float4 qv[16];
#pragma unroll
    for (int k = 0; k < 16; k++) qv[k] = __ldg(&q4[(size_t)qr * 64 + qf0 + 4 * k]);

    // ---- ctx staging: dots (weights via __ldg) + tf32 hi/lo split ----
    float sc_p = 0.f, c1_p = 0.f;
#pragma unroll
    for (int k = 0; k < 8; k++) {
        const int f  = cf + 8 * k;
        const int dg = f * 4;
        float4 v   = cv[k];
        float4 wcv = __ldg(&wc4[f]);
        float4 wiv = __ldg(&wi4[f]);
        sc_p += v.x * wcv.x + v.y * wcv.y + v.z * wcv.z + v.w * wcv.w;
        c1_p += v.x * wiv.x + v.y * wiv.y + v.z * wiv.z + v.w * wiv.w;
        float4 h, l;
        h.x = tf32r(v.x); l.x = tf32r(v.x - h.x);
        h.y = tf32r(v.y); l.y = tf32r(v.y - h.y);
        h.z = tf32r(v.z); l.z = tf32r(v.z - h.z);
        h.w = tf32r(v.w); l.w = tf32r(v.w - h.w);
        *(float4*)&dsm[OFF_CH + cr * SA + dg] = h;
        *(float4*)&dsm[OFF_CL + cr * SA + dg] = l;
    }
    sc_p += __shfl_xor_sync(0xffffffffu, sc_p, 1);
    sc_p += __shfl_xor_sync(0xffffffffu, sc_p, 2);
    sc_p += __shfl_xor_sync(0xffffffffu, sc_p, 4);
    c1_p += __shfl_xor_sync(0xffffffffu, c1_p, 1);
    c1_p += __shfl_xor_sync(0xffffffffu, c1_p, 2);
    c1_p += __shfl_xor_sync(0xffffffffu, c1_p, 4);
    if (cf == 0) { s_sc[cr] = sc_p; s_c1[cr] = c1_p; }

    // ---- q staging: dots, wp-premul, tf32 hi/lo split ----
    float sq_p = 0.f, q1_p = 0.f;
#pragma unroll
    for (int k = 0; k < 16; k++) {
        const int f  = qf0 + 4 * k;
        const int dg = f * 4;
        float4 v   = qv[k];
        float4 wqv = __ldg(&wq4[f]);
        float4 wmv = __ldg(&wm4[f]);
        float4 wpv = __ldg(&wp4[f]);
        sq_p += v.x * wqv.x + v.y * wqv.y + v.z * wqv.z + v.w * wqv.w;
        q1_p += v.x * wmv.x + v.y * wmv.y + v.z * wmv.z + v.w * wmv.w;
        float4 y = make_float4(v.x * wpv.x, v.y * wpv.y, v.z * wpv.z, v.w * wpv.w);
        float4 h, l;
        h.x = tf32r(y.x); l.x = tf32r(y.x - h.x);
        h.y = tf32r(y.y); l.y = tf32r(y.y - h.y);
        h.z = tf32r(y.z); l.z = tf32r(y.z - h.z);
        h.w = tf32r(y.w); l.w = tf32r(y.w - h.w);
        *(float4*)&dsm[OFF_QH + qr * SA + dg] = h;
        *(float4*)&dsm[OFF_QL + qr * SA + dg] = l;
    }
    sq_p += __shfl_xor_sync(0xffffffffu, sq_p, 1);
    sq_p += __shfl_xor_sync(0xffffffffu, sq_p, 2);
    q1_p += __shfl_xor_sync(0xffffffffu, q1_p, 1);
    q1_p += __shfl_xor_sync(0xffffffffu, q1_p, 2);
    if (qf0 == 0) { s_sq[qr] = sq_p; s_q1[qr] = q1_p; }
    __syncthreads();   // single pre-GEMM barrier

    // ---- tensor-core GEMM (unchanged from R11) ----
    {
        const int warp = tid >> 5, lid = tid & 31;
        const int g = lid >> 2, t = lid & 3;
        const int m  = (warp >> 2) * 16;
        const int n0 = (warp & 3) * 16;
        const uint32_t* Ch = (const uint32_t*)&dsm[OFF_CH];
        const uint32_t* Cl = (const uint32_t*)&dsm[OFF_CL];
        const uint32_t* Qh = (const uint32_t*)&dsm[OFF_QH];
        const uint32_t* Ql = (const uint32_t*)&dsm[OFF_QL];
        const int ra = (m + g) * SA, rb = (m + g + 8) * SA;
        const int nb0 = (n0 + g) * SA, nb1 = (n0 + 8 + g) * SA;

        float d0[2][4] = {}, d1[2][4] = {};
#pragma unroll 4
        for (int k0 = 0; k0 < DD; k0 += 8) {
            uint32_t ah[4], al[4], bh[2][2], bl[2][2];
            ah[0] = Ch[ra + k0 + t];     ah[1] = Ch[rb + k0 + t];
            ah[2] = Ch[ra + k0 + t + 4]; ah[3] = Ch[rb + k0 + t + 4];
            al[0] = Cl[ra + k0 + t];     al[1] = Cl[rb + k0 + t];
            al[2] = Cl[ra + k0 + t + 4]; al[3] = Cl[rb + k0 + t + 4];
            bh[0][0] = Qh[nb0 + k0 + t]; bh[0][1] = Qh[nb0 + k0 + t + 4];
            bh[1][0] = Qh[nb1 + k0 + t]; bh[1][1] = Qh[nb1 + k0 + t + 4];
            bl[0][0] = Ql[nb0 + k0 + t]; bl[0][1] = Ql[nb0 + k0 + t + 4];
            bl[1][0] = Ql[nb1 + k0 + t]; bl[1][1] = Ql[nb1 + k0 + t + 4];
#pragma unroll
            for (int s = 0; s < 2; s++) {
                mma8(d0[s], ah, bh[s]);
                mma8(d1[s], ah, bl[s]);
                mma8(d1[s], al, bh[s]);
            }
        }
#pragma unroll
        for (int s = 0; s < 2; s++) {
            const int nc = n0 + 8 * s + 2 * t;
            *(float2*)&dsm[OFF_S + (m + g) * SS + nc] =
                make_float2(d0[s][0] + d1[s][0], d0[s][1] + d1[s][1]);
            *(float2*)&dsm[OFF_S + (m + g + 8) * SS + nc] =
                make_float2(d0[s][2] + d1[s][2], d0[s][3] + d1[s][3]);
        }
    }
    __syncthreads();   // S visible

    // ---- per-row softmax; eager xyz output; block-local rowmax/U collection ----
    const int ti_ = tid >> 4;
    const int tj_ = tid & 15;
    const float bias = __ldg(att_b);
    const int4 mv = __ldg(&((const int4*)(mask + b * LQ))[tj_]);
    float myq1[4], addj[4];
    {
        float pen0 = -NEG_BIG * (1.0f - (float)mv.x);
        float pen1 = -NEG_BIG * (1.0f - (float)mv.y);
        float pen2 = -NEG_BIG * (1.0f - (float)mv.z);
        float pen3 = -NEG_BIG * (1.0f - (float)mv.w);
        int j = tj_ * 4;
        myq1[0] = s_q1[j];     addj[0] = s_sq[j]     + pen0 + bias;
        myq1[1] = s_q1[j + 1]; addj[1] = s_sq[j + 1] + pen1 + bias;
        myq1[2] = s_q1[j + 2]; addj[2] = s_sq[j + 2] + pen2 + bias;
        myq1[3] = s_q1[j + 3]; addj[3] = s_sq[j + 3] + pen3 + bias;
    }
#pragma unroll
    for (int a = 0; a < 2; a++) {
        int i = ti_ * 2 + a;
        float sci = s_sc[i];
        float4 sv = *(const float4*)&dsm[OFF_S + i * SS + tj_ * 4];
        float l[4], mx = -INFINITY;
        l[0] = sv.x + sci + addj[0];
        l[1] = sv.y + sci + addj[1];
        l[2] = sv.z + sci + addj[2];
        l[3] = sv.w + sci + addj[3];
#pragma unroll
        for (int e = 0; e < 4; e++) mx = fmaxf(mx, l[e]);
#pragma unroll
        for (int s = 1; s < 16; s <<= 1)
            mx = fmaxf(mx, __shfl_xor_sync(0xffffffffu, mx, s));
        float num = 0.f, den = 0.f;
#pragma unroll
        for (int e = 0; e < 4; e++) {
            float ev = __expf(l[e] - mx);
            num += ev * myq1[e];
            den += ev;
        }
#pragma unroll
        for (int s = 1; s < 16; s <<= 1) {
            num += __shfl_xor_sync(0xffffffffu, num, s);
            den += __shfl_xor_sync(0xffffffffu, den, s);
        }
        if (tj_ == 0) {
            float U = num / den;
            float c1 = s_c1[i];
            int gi = b * LC + i0 + i;
            g_U[gi] = U;
            s_m[i]  = mx;
            s_u[i]  = U;
            // eager: out.xyz (H-independent)
            float* o = (float*)out + (size_t)gi * 4;
            o[0] = c1; o[1] = U; o[2] = c1 * U;
        }
    }
    __syncthreads();

    // ---- block partial aggregate (warp 0): mloc, ploc, uloc ----
    if (tid < 32) {
        float m_i = s_m[tid], c1_i = s_c1[tid];
        float mloc = m_i;
#pragma unroll
        for (int s = 16; s > 0; s >>= 1)
            mloc = fmaxf(mloc, __shfl_xor_sync(0xffffffffu, mloc, s));
        float e = __expf(m_i - mloc);
        float p = e, u = e * c1_i;
#pragma unroll
        for (int s = 16; s > 0; s >>= 1) {
            p += __shfl_xor_sync(0xffffffffu, p, s);
            u += __shfl_xor_sync(0xffffffffu, u, s);
        }
        if (tid == 0) {
            float4* gp = (float4*)&g_part[(b * 16 + blockIdx.x) * 4];
            *gp = make_float4(mloc, p, u, 0.f);
        }
    }

    // ---- handoff ----
    __threadfence();
    __syncthreads();
    if (tid == 0) s_last = (atomicAdd(&g_cnt[b], 1u) == 15u) ? 1u : 0u;
    __syncthreads();
    if (!s_last) return;
    __threadfence();   // acquire side

    // issue g_U loads early (overlap with triple reduce)
    float u0 = __ldcg(&g_U[b * LC + tid]);
    float u1 = __ldcg(&g_U[b * LC + tid + NT]);

    if (tid < 16) {
        float4 tp = *(const float4*)&g_part[(b * 16 + tid) * 4];
        float M = tp.x;
#pragma unroll
        for (int s = 8; s > 0; s >>= 1)
            M = fmaxf(M, __shfl_xor_sync(0x0000ffffu, M, s));
        float sc = __expf(tp.x - M);
        float den = tp.y * sc, num = tp.z * sc;
#pragma unroll
        for (int s = 8; s > 0; s >>= 1) {
            den += __shfl_xor_sync(0x0000ffffu, den, s);
            num += __shfl_xor_sync(0x0000ffffu, num, s);
        }
        if (tid == 0) {
            s_red[0] = num / den;
            g_cnt[b] = 0;   // reset for next replay
        }
    }
    __syncthreads();
    const float H = s_red[0];

    // fill out.w = U * H for all 512 rows of this batch
    ((float*)out)[(size_t)(b * LC + tid) * 4 + 3]      = u0 * H;
    ((float*)out)[(size_t)(b * LC + tid + NT) * 4 + 3] = u1 * H;
}

extern "C" void kernel_launch(void* const* d_in, const int* in_sizes, int n_in,
                              void* d_out, int out_size)
{
    const float* ctx   = (const float*)d_in[0];  // (8,512,256)
    const float* qst   = (const float*)d_in[1];  // (8,64,256)
    const int*   mask  = (const int*)d_in[2];    // (8,64)
    const float* att_w = (const float*)d_in[3];  // (768,)
    const float* att_b = (const float*)d_in[4];  // (1,)
    const float* w_in  = (const float*)d_in[5];  // (256,)
    const float* w_mem = (const float*)d_in[6];  // (256,)
    float* out = (float*)d_out;                  // (8,512,4)

    cudaFuncSetAttribute(bi_attn_fused,
                         cudaFuncAttributeMaxDynamicSharedMemorySize, DYN_BYTES);
    dim3 grid(LC / TI, BB);
    bi_attn_fused<<<grid, NT, DYN_BYTES>>>(ctx, qst, mask, att_w, att_b,
                                           w_in, w_mem, out);
}

// round 14
// speedup vs baseline: 1.2739x; 1.0021x over previous
#include <cuda_runtime.h>
#include <cstdint>
#include <math.h>

#define BB 8
#define LC 512
#define LQ 64
#define DD 256
#define TI 32
#define NT 256
#define SA 260                  // hi/lo tile row stride (words): conflict-free frag loads
#define SS 68                   // S tile row stride
#define NEG_BIG 1e30f

// dynamic smem layout (float offsets)
#define OFF_CH 0                          // ctx hi  [32][SA]
#define OFF_CL (OFF_CH + TI * SA)         // ctx lo
#define OFF_QH (OFF_CL + TI * SA)         // (wp*q) hi [64][SA]
#define OFF_QL (OFF_QH + LQ * SA)         // (wp*q) lo
#define OFF_S  (OFF_QL + LQ * SA)         // S [32][SS]
#define DYN_FLOATS (OFF_S + TI * SS)
#define DYN_BYTES  (DYN_FLOATS * 4)       // ~208 KB

__device__ float g_part[BB * 16 * 4];     // (mloc, ploc, uloc, pad) per block
__device__ unsigned int g_cnt[BB];
__device__ unsigned int g_cnt2[BB];

__device__ __forceinline__ float tf32r(float x) {
    float r;
    asm("cvt.rna.tf32.f32 %0, %1;" : "=f"(r) : "f"(x));
    return r;
}
__device__ __forceinline__ void mma8(float* d, const uint32_t* a, const uint32_t* bb) {
    asm volatile(
        "mma.sync.aligned.m16n8k8.row.col.f32.tf32.tf32.f32 "
        "{%0,%1,%2,%3}, {%4,%5,%6,%7}, {%8,%9}, {%0,%1,%2,%3};"
        : "+f"(d[0]), "+f"(d[1]), "+f"(d[2]), "+f"(d[3])
        : "r"(a[0]), "r"(a[1]), "r"(a[2]), "r"(a[3]), "r"(bb[0]), "r"(bb[1]));
}

__global__ __launch_bounds__(NT, 1) void bi_attn_fused(
    const float* __restrict__ ctx, const float* __restrict__ qst,
    const int* __restrict__ mask, const float* __restrict__ att_w,
    const float* __restrict__ att_b, const float* __restrict__ w_in,
    const float* __restrict__ w_mem, float* __restrict__ out)
{
    extern __shared__ __align__(128) float dsm[];
    __shared__ float s_sc[TI], s_c1[TI], s_sq[LQ], s_q1[LQ];
    __shared__ float s_m[TI], s_u[TI];
    __shared__ float s_red[4];

    const int b   = blockIdx.y;
    const int i0  = blockIdx.x * TI;
    const int tid = threadIdx.x;

    const float4* ctx4 = (const float4*)(ctx + ((size_t)b * LC + i0) * DD);
    const float4* q4   = (const float4*)(qst + (size_t)b * LQ * DD);
    const float4* wc4  = (const float4*)att_w;          // [0,64)
    const float4* wq4  = wc4 + 64;                      // att_w[256..512)
    const float4* wp4  = wc4 + 128;                     // att_w[512..768)
    const float4* wi4  = (const float4*)w_in;
    const float4* wm4  = (const float4*)w_mem;

    const int cr  = tid >> 3, cf  = tid & 7;   // ctx: 32 rows x 8 thr (f = cf + 8k)
    const int qr  = tid >> 2, qf0 = tid & 3;   // q:   64 rows x 4 thr (f = qf0 + 4k)
    const int ti_ = tid >> 4, tj_ = tid & 15;

    // tiny operands early
    const float bias = __ldg(att_b);
    const int4 mv = __ldg(&((const int4*)(mask + b * LQ))[tj_]);

    // ---- double-buffered staging: groups of 4 float4 in flight ----
    float4 cbuf[2][4], qbuf[2][4];
#pragma unroll
    for (int k = 0; k < 4; k++) cbuf[0][k] = __ldg(&ctx4[(size_t)cr * 64 + cf + 8 * k]);
#pragma unroll
    for (int k = 0; k < 4; k++) qbuf[0][k] = __ldg(&q4[(size_t)qr * 64 + qf0 + 4 * k]);

    float sc_p = 0.f, c1_p = 0.f;
#pragma unroll
    for (int g = 0; g < 2; g++) {
        if (g < 1)
#pragma unroll
            for (int k = 0; k < 4; k++)
                cbuf[1][k] = __ldg(&ctx4[(size_t)cr * 64 + cf + 8 * (4 + k)]);
#pragma unroll
        for (int k = 0; k < 4; k++) {
            const int f  = cf + 8 * (4 * g + k);
            const int dg = f * 4;
            float4 v   = cbuf[g & 1][k];
            float4 wcv = __ldg(&wc4[f]);
            float4 wiv = __ldg(&wi4[f]);
            sc_p += v.x * wcv.x + v.y * wcv.y + v.z * wcv.z + v.w * wcv.w;
            c1_p += v.x * wiv.x + v.y * wiv.y + v.z * wiv.z + v.w * wiv.w;
            float4 h, l;
            h.x = tf32r(v.x); l.x = tf32r(v.x - h.x);
            h.y = tf32r(v.y); l.y = tf32r(v.y - h.y);
            h.z = tf32r(v.z); l.z = tf32r(v.z - h.z);
            h.w = tf32r(v.w); l.w = tf32r(v.w - h.w);
            *(float4*)&dsm[OFF_CH + cr * SA + dg] = h;
            *(float4*)&dsm[OFF_CL + cr * SA + dg] = l;
        }
    }
    sc_p += __shfl_xor_sync(0xffffffffu, sc_p, 1);
    sc_p += __shfl_xor_sync(0xffffffffu, sc_p, 2);
    sc_p += __shfl_xor_sync(0xffffffffu, sc_p, 4);
    c1_p += __shfl_xor_sync(0xffffffffu, c1_p, 1);
    c1_p += __shfl_xor_sync(0xffffffffu, c1_p, 2);
    c1_p += __shfl_xor_sync(0xffffffffu, c1_p, 4);
    if (cf == 0) { s_sc[cr] = sc_p; s_c1[cr] = c1_p; }

    float sq_p = 0.f, q1_p = 0.f;
#pragma unroll
    for (int g = 0; g < 4; g++) {
        if (g < 3)
#pragma unroll
            for (int k = 0; k < 4; k++)
                qbuf[(g + 1) & 1][k] =
                    __ldg(&q4[(size_t)qr * 64 + qf0 + 4 * (4 * (g + 1) + k)]);
#pragma unroll
        for (int k = 0; k < 4; k++) {
            const int f  = qf0 + 4 * (4 * g + k);
            const int dg = f * 4;
            float4 v   = qbuf[g & 1][k];
            float4 wqv = __ldg(&wq4[f]);
            float4 wmv = __ldg(&wm4[f]);
            float4 wpv = __ldg(&wp4[f]);
            sq_p += v.x * wqv.x + v.y * wqv.y + v.z * wqv.z + v.w * wqv.w;
            q1_p += v.x * wmv.x + v.y * wmv.y + v.z * wmv.z + v.w * wmv.w;
            float4 y = make_float4(v.x * wpv.x, v.y * wpv.y, v.z * wpv.z, v.w * wpv.w);
            float4 h, l;
            h.x = tf32r(y.x); l.x = tf32r(y.x - h.x);
            h.y = tf32r(y.y); l.y = tf32r(y.y - h.y);
            h.z = tf32r(y.z); l.z = tf32r(y.z - h.z);
            h.w = tf32r(y.w); l.w = tf32r(y.w - h.w);
            *(float4*)&dsm[OFF_QH + qr * SA + dg] = h;
            *(float4*)&dsm[OFF_QL + qr * SA + dg] = l;
        }
    }
    sq_p += __shfl_xor_sync(0xffffffffu, sq_p, 1);
    sq_p += __shfl_xor_sync(0xffffffffu, sq_p, 2);
    q1_p += __shfl_xor_sync(0xffffffffu, q1_p, 1);
    q1_p += __shfl_xor_sync(0xffffffffu, q1_p, 2);
    if (qf0 == 0) { s_sq[qr] = sq_p; s_q1[qr] = q1_p; }
    __syncthreads();   // single pre-GEMM barrier

    // ---- tensor-core GEMM (unchanged) ----
    {
        const int warp = tid >> 5, lid = tid & 31;
        const int g = lid >> 2, t = lid & 3;
        const int m  = (warp >> 2) * 16;
        const int n0 = (warp & 3) * 16;
        const uint32_t* Ch = (const uint32_t*)&dsm[OFF_CH];
        const uint32_t* Cl = (const uint32_t*)&dsm[OFF_CL];
        const uint32_t* Qh = (const uint32_t*)&dsm[OFF_QH];
        const uint32_t* Ql = (const uint32_t*)&dsm[OFF_QL];
        const int ra = (m + g) * SA, rb = (m + g + 8) * SA;
        const int nb0 = (n0 + g) * SA, nb1 = (n0 + 8 + g) * SA;

        float d0[2][4] = {}, d1[2][4] = {};
#pragma unroll 4
        for (int k0 = 0; k0 < DD; k0 += 8) {
            uint32_t ah[4], al[4], bh[2][2], bl[2][2];
            ah[0] = Ch[ra + k0 + t];     ah[1] = Ch[rb + k0 + t];
            ah[2] = Ch[ra + k0 + t + 4]; ah[3] = Ch[rb + k0 + t + 4];
            al[0] = Cl[ra + k0 + t];     al[1] = Cl[rb + k0 + t];
            al[2] = Cl[ra + k0 + t + 4]; al[3] = Cl[rb + k0 + t + 4];
            bh[0][0] = Qh[nb0 + k0 + t]; bh[0][1] = Qh[nb0 + k0 + t + 4];
            bh[1][0] = Qh[nb1 + k0 + t]; bh[1][1] = Qh[nb1 + k0 + t + 4];
            bl[0][0] = Ql[nb0 + k0 + t]; bl[0][1] = Ql[nb0 + k0 + t + 4];
            bl[1][0] = Ql[nb1 + k0 + t]; bl[1][1] = Ql[nb1 + k0 + t + 4];
#pragma unroll
            for (int s = 0; s < 2; s++) {
                mma8(d0[s], ah, bh[s]);
                mma8(d1[s], ah, bl[s]);
                mma8(d1[s], al, bh[s]);
            }
        }
#pragma unroll
        for (int s = 0; s < 2; s++) {
            const int nc = n0 + 8 * s + 2 * t;
            *(float2*)&dsm[OFF_S + (m + g) * SS + nc] =
                make_float2(d0[s][0] + d1[s][0], d0[s][1] + d1[s][1]);
            *(float2*)&dsm[OFF_S + (m + g + 8) * SS + nc] =
                make_float2(d0[s][2] + d1[s][2], d0[s][3] + d1[s][3]);
        }
    }
    __syncthreads();   // S visible

    // ---- per-row softmax -> s_m / s_u ----
    float myq1[4], addj[4];
    {
        float pen0 = -NEG_BIG * (1.0f - (float)mv.x);
        float pen1 = -NEG_BIG * (1.0f - (float)mv.y);
        float pen2 = -NEG_BIG * (1.0f - (float)mv.z);
        float pen3 = -NEG_BIG * (1.0f - (float)mv.w);
        int j = tj_ * 4;
        myq1[0] = s_q1[j];     addj[0] = s_sq[j]     + pen0 + bias;
        myq1[1] = s_q1[j + 1]; addj[1] = s_sq[j + 1] + pen1 + bias;
        myq1[2] = s_q1[j + 2]; addj[2] = s_sq[j + 2] + pen2 + bias;
        myq1[3] = s_q1[j + 3]; addj[3] = s_sq[j + 3] + pen3 + bias;
    }
#pragma unroll
    for (int a = 0; a < 2; a++) {
        int i = ti_ * 2 + a;
        float sci = s_sc[i];
        float4 sv = *(const float4*)&dsm[OFF_S + i * SS + tj_ * 4];
        float l[4], mx = -INFINITY;
        l[0] = sv.x + sci + addj[0];
        l[1] = sv.y + sci + addj[1];
        l[2] = sv.z + sci + addj[2];
        l[3] = sv.w + sci + addj[3];
#pragma unroll
        for (int e = 0; e < 4; e++) mx = fmaxf(mx, l[e]);
#pragma unroll
        for (int s = 1; s < 16; s <<= 1)
            mx = fmaxf(mx, __shfl_xor_sync(0xffffffffu, mx, s));
        float num = 0.f, den = 0.f;
#pragma unroll
        for (int e = 0; e < 4; e++) {
            float ev = __expf(l[e] - mx);
            num += ev * myq1[e];
            den += ev;
        }
#pragma unroll
        for (int s = 1; s < 16; s <<= 1) {
            num += __shfl_xor_sync(0xffffffffu, num, s);
            den += __shfl_xor_sync(0xffffffffu, den, s);
        }
        if (tj_ == 0) { s_m[i] = mx; s_u[i] = num / den; }
    }
    __syncthreads();   // s_m/s_u/s_c1 ready

    // ---- publish block partial, then spin for all 16 partials of batch ----
    if (tid < 32) {
        float m_i = s_m[tid], c1_i = s_c1[tid];
        float mloc = m_i;
#pragma unroll
        for (int s = 16; s > 0; s >>= 1)
            mloc = fmaxf(mloc, __shfl_xor_sync(0xffffffffu, mloc, s));
        float e = __expf(m_i - mloc);
        float p = e, u = e * c1_i;
#pragma unroll
        for (int s = 16; s > 0; s >>= 1) {
            p += __shfl_xor_sync(0xffffffffu, p, s);
            u += __shfl_xor_sync(0xffffffffu, u, s);
        }
        if (tid == 0) {
            *(float4*)&g_part[(b * 16 + blockIdx.x) * 4] = make_float4(mloc, p, u, 0.f);
            __threadfence();                 // release partial
            atomicAdd(&g_cnt[b], 1u);
            unsigned v;
            do {
                asm volatile("ld.global.acquire.gpu.u32 %0, [%1];"
                             : "=r"(v) : "l"(&g_cnt[b]) : "memory");
            } while (v < 16u);
        }
    }
    __syncthreads();   // everyone past the batch barrier
    __threadfence();   // order partial reads after acquire

    // ---- every block computes H from the 16 triples ----
    if (tid < 16) {
        float4 tp = __ldcg((const float4*)&g_part[(b * 16 + tid) * 4]);
        float M = tp.x;
#pragma unroll
        for (int s = 8; s > 0; s >>= 1)
            M = fmaxf(M, __shfl_xor_sync(0x0000ffffu, M, s));
        float scl = __expf(tp.x - M);
        float den = tp.y * scl, num = tp.z * scl;
#pragma unroll
        for (int s = 8; s > 0; s >>= 1) {
            den += __shfl_xor_sync(0x0000ffffu, den, s);
            num += __shfl_xor_sync(0x0000ffffu, num, s);
        }
        if (tid == 0) s_red[0] = num / den;
    }
    __syncthreads();
    const float H = s_red[0];

    // ---- one coalesced 512B output burst for this block's 32 rows ----
    if (tid < 32) {
        float U = s_u[tid], c1 = s_c1[tid];
        ((float4*)out)[(size_t)b * LC + i0 + tid] = make_float4(c1, U, c1 * U, U * H);
    }

    // ---- replay-safe counter reset ----
    if (tid == 0) {
        unsigned old = atomicAdd(&g_cnt2[b], 1u);
        if (old == 15u) { g_cnt[b] = 0; g_cnt2[b] = 0; }
    }
}

extern "C" void kernel_launch(void* const* d_in, const int* in_sizes, int n_in,
                              void* d_out, int out_size)
{
    const float* ctx   = (const float*)d_in[0];  // (8,512,256)
    const float* qst   = (const float*)d_in[1];  // (8,64,256)
    const int*   mask  = (const int*)d_in[2];    // (8,64)
    const float* att_w = (const float*)d_in[3];  // (768,)
    const float* att_b = (const float*)d_in[4];  // (1,)
    const float* w_in  = (const float*)d_in[5];  // (256,)
    const float* w_mem = (const float*)d_in[6];  // (256,)
    float* out = (float*)d_out;                  // (8,512,4)

    cudaFuncSetAttribute(bi_attn_fused,
                         cudaFuncAttributeMaxDynamicSharedMemorySize, DYN_BYTES);
    dim3 grid(LC / TI, BB);
    bi_attn_fused<<<grid, NT, DYN_BYTES>>>(ctx, qst, mask, att_w, att_b,
                                           w_in, w_mem, out);
}